// round 8
// baseline (speedup 1.0000x reference)
#include <cuda_runtime.h>
#include <cuda_bf16.h>
#include <stdint.h>
#include <math.h>

// Problem constants
#define Bdim 2
#define Tdim 1536
#define Cdim 1536
#define Hdim 8
#define Kdim 64
#define Vdim 192
#define HK   512
#define HV   1536
#define L2   3071     // 2*T-1
#define ZN   16       // B*H
#define CP   768      // 1536/2 pairs
#define KP   32       // 64/2 pairs

// ---------------- scratch: packed bf16x2 hi/lo, [row][kpair] ----------------
__device__ uint32_t xs_h[(size_t)3072 * CP],  xs_l[(size_t)3072 * CP];
__device__ uint32_t wq_h[(size_t)HK * CP],    wq_l[(size_t)HK * CP];
__device__ uint32_t wk_h[(size_t)HK * CP],    wk_l[(size_t)HK * CP];
__device__ uint32_t wv_h[(size_t)HV * CP],    wv_l[(size_t)HV * CP];
__device__ uint32_t wo_h[(size_t)HV * CP],    wo_l[(size_t)HV * CP];
__device__ uint32_t qw_h[(size_t)ZN * Tdim * KP], qw_l[(size_t)ZN * Tdim * KP];
__device__ uint32_t qr_h[(size_t)ZN * Tdim * KP], qr_l[(size_t)ZN * Tdim * KP];
__device__ uint32_t kk_h[(size_t)ZN * Tdim * KP], kk_l[(size_t)ZN * Tdim * KP];
__device__ uint32_t rk_h[(size_t)Hdim * L2 * KP], rk_l[(size_t)Hdim * L2 * KP];
__device__ float    g_v [(size_t)ZN * Tdim * Vdim];
__device__ uint32_t vt_h[(size_t)ZN * Vdim * CP], vt_l[(size_t)ZN * Vdim * CP];
__device__ uint32_t p_h [(size_t)ZN * Tdim * CP], p_l [(size_t)ZN * Tdim * CP];
__device__ uint32_t at_h[(size_t)3072 * CP],  at_l[(size_t)3072 * CP];
__device__ float    g_logits[(size_t)ZN * Tdim * Tdim];

// ---------------- helpers ----------------
__device__ __forceinline__ uint32_t pack2(float a, float b) {
    uint32_t r;
    asm("cvt.rn.bf16x2.f32 %0, %1, %2;" : "=r"(r) : "f"(b), "f"(a));
    return r;
}
__device__ __forceinline__ void split2(float x0, float x1, uint32_t& h, uint32_t& l) {
    float h0 = __bfloat162float(__float2bfloat16(x0));
    float h1 = __bfloat162float(__float2bfloat16(x1));
    h = pack2(h0, h1);
    l = pack2(x0 - h0, x1 - h1);
}
__device__ __forceinline__ void mma_bf16(float* d, const uint32_t* a, const uint32_t* b) {
    asm volatile(
        "mma.sync.aligned.m16n8k16.row.col.f32.bf16.bf16.f32 "
        "{%0,%1,%2,%3}, {%4,%5,%6,%7}, {%8,%9}, {%0,%1,%2,%3};"
        : "+f"(d[0]), "+f"(d[1]), "+f"(d[2]), "+f"(d[3])
        : "r"(a[0]), "r"(a[1]), "r"(a[2]), "r"(a[3]), "r"(b[0]), "r"(b[1]));
}
__device__ __forceinline__ void cpa16(uint32_t dst, const void* src) {
    asm volatile("cp.async.cg.shared.global [%0], [%1], 16;" :: "r"(dst), "l"(src));
}
#define CP_COMMIT() asm volatile("cp.async.commit_group;")
__device__ __forceinline__ void ldm4(uint32_t* r, uint32_t addr) {
    asm volatile("ldmatrix.sync.aligned.m8n8.x4.shared.b16 {%0,%1,%2,%3}, [%4];"
                 : "=r"(r[0]), "=r"(r[1]), "=r"(r[2]), "=r"(r[3]) : "r"(addr));
}

// ---------------- mma.sync bf16x3 GEMM: 128xNT tile, k-chunk 32, ldmatrix --------
// smem stage: Ah[128*80] Al[128*80] Bh[NT*80] Bl[NT*80]
#define AROWB 80
#define A_LO  10240
#define B_OFF 20480

// MODE 0: x@[Wq|Wk] -> qw,qr,kk | 2: x@Wv -> g_v | 3: attn@Wo+bo -> out
// MODE 4: P@V -> at | 5: qw@k^T -> logits | 6: qr@rk^T banded scatter-add
template <int MODE, int NT>
__global__ __launch_bounds__(256) void mma_gemm(
    const float* __restrict__ bias0, const float* __restrict__ bias1,
    float* __restrict__ outp)
{
    constexpr int B_LO = NT * 80;
    constexpr int STG  = B_OFF + 2 * B_LO;
    constexpr int NI   = NT / 16;     // n-subtiles of 8 per warp
    constexpr int NG   = NT / 32;     // 16-row B ldmatrix groups per warp

    extern __shared__ uint8_t dsm[];

    const int z   = blockIdx.z;
    const int m0  = blockIdx.y * 128;
    const int n0  = blockIdx.x * NT;
    const int tid = threadIdx.x;
    const int lane = tid & 31, warp = tid >> 5;
    const int wm = warp >> 1, wn = warp & 1;

    const uint32_t *Ah_g, *Al_g, *Bh_g, *Bl_g;
    int ldpA, ldpB, nchunks;
    bool isQ = true;
    int n0b = n0;
    if (MODE == 0) {
        Ah_g = xs_h; Al_g = xs_l;
        isQ = (n0 < HK);
        if (isQ) { Bh_g = wq_h; Bl_g = wq_l; }
        else     { Bh_g = wk_h; Bl_g = wk_l; n0b = n0 - HK; }
        ldpA = CP; ldpB = CP; nchunks = Cdim / 32;
    }
    else if (MODE == 2) { Ah_g = xs_h; Al_g = xs_l; Bh_g = wv_h; Bl_g = wv_l; ldpA = CP; ldpB = CP; nchunks = Cdim / 32; }
    else if (MODE == 3) { Ah_g = at_h; Al_g = at_l; Bh_g = wo_h; Bl_g = wo_l; ldpA = CP; ldpB = CP; nchunks = HV / 32; }
    else if (MODE == 4) { Ah_g = p_h + (size_t)z * Tdim * CP; Al_g = p_l + (size_t)z * Tdim * CP;
                          Bh_g = vt_h + (size_t)z * Vdim * CP; Bl_g = vt_l + (size_t)z * Vdim * CP;
                          ldpA = CP; ldpB = CP; nchunks = Tdim / 32; }
    else if (MODE == 5) { Ah_g = qw_h + (size_t)z * Tdim * KP; Al_g = qw_l + (size_t)z * Tdim * KP;
                          Bh_g = kk_h + (size_t)z * Tdim * KP; Bl_g = kk_l + (size_t)z * Tdim * KP;
                          ldpA = KP; ldpB = KP; nchunks = Kdim / 32; }
    else                { Ah_g = qr_h + (size_t)z * Tdim * KP; Al_g = qr_l + (size_t)z * Tdim * KP;
                          Bh_g = rk_h + (size_t)(z & 7) * L2 * KP; Bl_g = rk_l + (size_t)(z & 7) * L2 * KP;
                          ldpA = KP; ldpB = KP; nchunks = Kdim / 32; }

    // column base: r-space for MODE 6, else local n
    const int cb = (MODE == 6) ? (1408 - m0 + n0) : n0b;

    const uint32_t sb = (uint32_t)__cvta_generic_to_shared(dsm);

    // ---- producer assignments ----
    const int ar = tid >> 1, ac2 = (tid & 1) * 2;
    const size_t aoff0 = (size_t)(m0 + ar) * ldpA + ac2 * 4;
    const uint32_t adst0 = sb + ar * AROWB + ac2 * 16;

    size_t boff0;
    uint32_t bdst0;
    if (NT == 128) {
        int br = tid >> 1, bc2 = (tid & 1) * 2;
        int gr = cb + br;
        if (MODE == 6 && gr > L2 - 1) gr = L2 - 1;
        boff0 = (size_t)gr * ldpB + bc2 * 4;
        bdst0 = sb + B_OFF + br * AROWB + bc2 * 16;
    } else {
        int br = tid >> 2, bc = tid & 3;
        int gr = cb + br;
        if (MODE == 6 && gr > L2 - 1) gr = L2 - 1;
        boff0 = (size_t)gr * ldpB + bc * 4;
        bdst0 = sb + B_OFF + br * AROWB + bc * 16;
    }

    auto fill = [&](int s, int c) {
        const uint32_t st = s * STG;
        const size_t ko = (size_t)c * 16;
        cpa16(adst0 + st,             Ah_g + aoff0 + ko);
        cpa16(adst0 + st + 16,        Ah_g + aoff0 + ko + 4);
        cpa16(adst0 + st + A_LO,      Al_g + aoff0 + ko);
        cpa16(adst0 + st + A_LO + 16, Al_g + aoff0 + ko + 4);
        if (NT == 128) {
            cpa16(bdst0 + st,             Bh_g + boff0 + ko);
            cpa16(bdst0 + st + 16,        Bh_g + boff0 + ko + 4);
            cpa16(bdst0 + st + B_LO,      Bl_g + boff0 + ko);
            cpa16(bdst0 + st + B_LO + 16, Bl_g + boff0 + ko + 4);
        } else {
            cpa16(bdst0 + st,        Bh_g + boff0 + ko);
            cpa16(bdst0 + st + B_LO, Bl_g + boff0 + ko);
        }
        CP_COMMIT();
    };

    // ---- consumer lane addressing ----
    const int mat = lane >> 3, rIn = lane & 7;
    const int mrow = (mat & 1) * 8 + rIn;
    const int colb = (mat >> 1) * 16;
    const uint32_t aAddr = sb + (uint32_t)((wm * 32 + mrow) * AROWB + colb);
    const uint32_t bAddr = sb + (uint32_t)(B_OFF + (wn * (NT / 2) + mrow) * AROWB + colb);

    float acc[2][NI][4] = {};

    fill(0, 0);
    if (nchunks > 1) fill(1, 1);

    for (int c = 0; c < nchunks; c++) {
        const int s = c & 1;
        if (c + 1 < nchunks) asm volatile("cp.async.wait_group 1;");
        else                 asm volatile("cp.async.wait_group 0;");
        __syncthreads();

        const uint32_t st = s * STG;
        #pragma unroll
        for (int kh = 0; kh < 2; kh++) {
            uint32_t ah[2][4], al[2][4], bh[NG][4], bl[NG][4];
            ldm4(ah[0], aAddr + st + kh * 32);
            ldm4(ah[1], aAddr + st + 16 * AROWB + kh * 32);
            ldm4(al[0], aAddr + st + A_LO + kh * 32);
            ldm4(al[1], aAddr + st + A_LO + 16 * AROWB + kh * 32);
            #pragma unroll
            for (int g = 0; g < NG; g++) {
                ldm4(bh[g], bAddr + st + g * 16 * AROWB + kh * 32);
                ldm4(bl[g], bAddr + st + B_LO + g * 16 * AROWB + kh * 32);
            }
            #pragma unroll
            for (int mi = 0; mi < 2; mi++)
                #pragma unroll
                for (int ni = 0; ni < NI; ni++) {
                    const int ng = ni >> 1, j = ni & 1;
                    uint32_t b2h[2] = { bh[ng][j], bh[ng][j + 2] };
                    uint32_t b2l[2] = { bl[ng][j], bl[ng][j + 2] };
                    mma_bf16(acc[mi][ni], ah[mi], b2h);
                    mma_bf16(acc[mi][ni], ah[mi], b2l);
                    mma_bf16(acc[mi][ni], al[mi], b2h);
                }
        }
        __syncthreads();
        if (c + 2 < nchunks) fill(s, c + 2);
    }

    // ---------------- epilogue ----------------
    #pragma unroll
    for (int mi = 0; mi < 2; mi++) {
        #pragma unroll
        for (int ni = 0; ni < NI; ni++) {
            #pragma unroll
            for (int hh = 0; hh < 2; hh++) {
                const int row = m0 + wm * 32 + mi * 16 + (lane >> 2) + hh * 8;
                const int col = cb + wn * (NT / 2) + ni * 8 + 2 * (lane & 3);
                float v0 = acc[mi][ni][hh * 2 + 0];
                float v1 = acc[mi][ni][hh * 2 + 1];

                if (MODE == 0) {
                    int bb = row / Tdim, t = row % Tdim;
                    int h = col >> 6, kw = col & 63;
                    size_t idx = (((size_t)(bb * Hdim + h)) * Tdim + t) * KP + (kw >> 1);
                    if (isQ) {
                        float q0 = v0 * 0.125f, q1 = v1 * 0.125f;
                        uint32_t hw, lw;
                        split2(q0 + bias0[col], q1 + bias0[col + 1], hw, lw);
                        qw_h[idx] = hw; qw_l[idx] = lw;
                        split2(q0 + bias1[col], q1 + bias1[col + 1], hw, lw);
                        qr_h[idx] = hw; qr_l[idx] = lw;
                    } else {
                        uint32_t hw, lw;
                        split2(v0, v1, hw, lw);
                        kk_h[idx] = hw; kk_l[idx] = lw;
                    }
                } else if (MODE == 2) {
                    int bb = row / Tdim, t = row % Tdim;
                    int h = col / Vdim, vv = col % Vdim;
                    *(float2*)&g_v[(((size_t)(bb * Hdim + h)) * Tdim + t) * Vdim + vv] = make_float2(v0, v1);
                } else if (MODE == 3) {
                    *(float2*)&outp[(size_t)row * HV + col] = make_float2(v0 + bias0[col], v1 + bias0[col + 1]);
                } else if (MODE == 4) {
                    int bb = z >> 3, h = z & 7;
                    int hv = h * Vdim + col;
                    size_t idx = (size_t)(bb * Tdim + row) * CP + (hv >> 1);
                    uint32_t hw, lw;
                    split2(v0, v1, hw, lw);
                    at_h[idx] = hw; at_l[idx] = lw;
                } else if (MODE == 5) {
                    *(float2*)&g_logits[((size_t)z * Tdim + row) * Tdim + col] = make_float2(v0, v1);
                } else { // MODE 6 scatter-add: s = r + t - (T-1)
                    float* pl = g_logits + ((size_t)z * Tdim + row) * Tdim;
                    int s0 = col + row - (Tdim - 1);
                    if (s0 >= 0 && s0 < Tdim) pl[s0] += v0;
                    if (s0 + 1 >= 0 && s0 + 1 < Tdim) pl[s0 + 1] += v1;
                }
            }
        }
    }
}

// ---------------- prep kernels ----------------
__global__ void split_rows(const float* __restrict__ in, uint32_t* __restrict__ oh,
                           uint32_t* __restrict__ ol, size_t npairs)
{
    size_t i = (size_t)blockIdx.x * blockDim.x + threadIdx.x;
    if (i >= npairs) return;
    float2 v = ((const float2*)in)[i];
    split2(v.x, v.y, oh[i], ol[i]);
}

__global__ void split_T(const float* __restrict__ in, uint32_t* __restrict__ oh,
                        uint32_t* __restrict__ ol, int Kc, int N,
                        size_t in_zs, size_t out_zs)
{
    __shared__ float tile[32][33];
    const float* inz = in + (size_t)blockIdx.z * in_zs;
    uint32_t* ohz = oh + (size_t)blockIdx.z * out_zs;
    uint32_t* olz = ol + (size_t)blockIdx.z * out_zs;
    int k0 = blockIdx.y * 32, n0 = blockIdx.x * 32;
    int tid = threadIdx.x;
    #pragma unroll
    for (int i = 0; i < 4; i++) {
        int idx = tid + i * 256;
        int kr = idx >> 5, nn = idx & 31;
        tile[kr][nn] = inz[(size_t)(k0 + kr) * N + n0 + nn];
    }
    __syncthreads();
    #pragma unroll
    for (int i = 0; i < 2; i++) {
        int idx = tid + i * 256;
        int nn = idx >> 4, kp = idx & 15;
        uint32_t h, l;
        split2(tile[2 * kp][nn], tile[2 * kp + 1][nn], h, l);
        size_t o = (size_t)(n0 + nn) * (Kc / 2) + k0 / 2 + kp;
        ohz[o] = h; olz[o] = l;
    }
}

__global__ void rk_kernel(const float* __restrict__ Wr)
{
    __shared__ float cw[16];
    int r = blockIdx.x;
    int tid = threadIdx.x;
    if (tid < 16) {
        float pr = (float)exp(log((double)(Tdim + 1)) / 16.0);
        cw[tid] = powf(pr, (float)(tid + 1)) - 1.0f;
    }
    __syncthreads();
    float d  = (float)(r - (Tdim - 1));
    float ad = fabsf(d);
    float sg = (d > 0.f) ? 1.f : ((d < 0.f) ? -1.f : 0.f);
    int h = tid >> 5, kp = tid & 31;
    int c0 = h * 64 + 2 * kp;
    float a0 = 0.f, a1 = 0.f;
    #pragma unroll
    for (int i = 0; i < 16; i++)
        if (cw[i] > ad) {
            a0 += Wr[i * HK + c0]     + sg * Wr[(i + 16) * HK + c0];
            a1 += Wr[i * HK + c0 + 1] + sg * Wr[(i + 16) * HK + c0 + 1];
        }
    uint32_t hw, lw;
    split2(a0, a1, hw, lw);
    size_t idx = ((size_t)h * L2 + r) * KP + kp;
    rk_h[idx] = hw; rk_l[idx] = lw;
}

__global__ void softmax_kernel()
{
    const size_t row = blockIdx.x;
    const float4* p = (const float4*)(g_logits + row * Tdim);
    uint32_t* ph = p_h + row * CP;
    uint32_t* plo = p_l + row * CP;
    const int tid = threadIdx.x;
    __shared__ float red[4];

    float4 v[3];
    float m = -1e30f;
    #pragma unroll
    for (int e = 0; e < 3; e++) {
        v[e] = p[tid + e * 128];
        m = fmaxf(m, fmaxf(fmaxf(v[e].x, v[e].y), fmaxf(v[e].z, v[e].w)));
    }
    #pragma unroll
    for (int o = 16; o > 0; o >>= 1) m = fmaxf(m, __shfl_xor_sync(0xffffffffu, m, o));
    if ((tid & 31) == 0) red[tid >> 5] = m;
    __syncthreads();
    m = fmaxf(fmaxf(red[0], red[1]), fmaxf(red[2], red[3]));
    __syncthreads();

    float s = 0.f;
    #pragma unroll
    for (int e = 0; e < 3; e++) {
        v[e].x = __expf(v[e].x - m); v[e].y = __expf(v[e].y - m);
        v[e].z = __expf(v[e].z - m); v[e].w = __expf(v[e].w - m);
        s += v[e].x + v[e].y + v[e].z + v[e].w;
    }
    #pragma unroll
    for (int o = 16; o > 0; o >>= 1) s += __shfl_xor_sync(0xffffffffu, s, o);
    if ((tid & 31) == 0) red[tid >> 5] = s;
    __syncthreads();
    s = red[0] + red[1] + red[2] + red[3];
    float inv = 1.0f / s;
    #pragma unroll
    for (int e = 0; e < 3; e++) {
        float p0 = v[e].x * inv, p1 = v[e].y * inv, p2 = v[e].z * inv, p3 = v[e].w * inv;
        uint32_t h0, l0, h1, l1;
        split2(p0, p1, h0, l0);
        split2(p2, p3, h1, l1);
        int o = (tid + e * 128) * 2;
        *(uint2*)&ph[o]  = make_uint2(h0, h1);
        *(uint2*)&plo[o] = make_uint2(l0, l1);
    }
}

// ---------------- launch ----------------------------------------------------------
extern "C" void kernel_launch(void* const* d_in, const int* in_sizes, int n_in,
                              void* d_out, int out_size)
{
    const float* x   = (const float*)d_in[0];
    const float* Wq  = (const float*)d_in[1];
    const float* Wk  = (const float*)d_in[2];
    const float* Wv  = (const float*)d_in[3];
    const float* Wr  = (const float*)d_in[4];
    const float* rwb = (const float*)d_in[5];
    const float* rrb = (const float*)d_in[6];
    const float* Wo  = (const float*)d_in[7];
    const float* bo  = (const float*)d_in[8];
    float* out = (float*)d_out;

    uint32_t *d_xs_h, *d_xs_l, *d_wq_h, *d_wq_l, *d_wk_h, *d_wk_l;
    uint32_t *d_wv_h, *d_wv_l, *d_wo_h, *d_wo_l, *d_vt_h, *d_vt_l;
    float* d_gv;
    cudaGetSymbolAddress((void**)&d_xs_h, xs_h); cudaGetSymbolAddress((void**)&d_xs_l, xs_l);
    cudaGetSymbolAddress((void**)&d_wq_h, wq_h); cudaGetSymbolAddress((void**)&d_wq_l, wq_l);
    cudaGetSymbolAddress((void**)&d_wk_h, wk_h); cudaGetSymbolAddress((void**)&d_wk_l, wk_l);
    cudaGetSymbolAddress((void**)&d_wv_h, wv_h); cudaGetSymbolAddress((void**)&d_wv_l, wv_l);
    cudaGetSymbolAddress((void**)&d_wo_h, wo_h); cudaGetSymbolAddress((void**)&d_wo_l, wo_l);
    cudaGetSymbolAddress((void**)&d_vt_h, vt_h); cudaGetSymbolAddress((void**)&d_vt_l, vt_l);
    cudaGetSymbolAddress((void**)&d_gv, g_v);

    const int SM128 = 2 * (B_OFF + 2 * 128 * 80);   // 81920
    const int SM64  = 2 * (B_OFF + 2 * 64 * 80);    // 61440
    cudaFuncSetAttribute(mma_gemm<0,128>, cudaFuncAttributeMaxDynamicSharedMemorySize, SM128);
    cudaFuncSetAttribute(mma_gemm<2,128>, cudaFuncAttributeMaxDynamicSharedMemorySize, SM128);
    cudaFuncSetAttribute(mma_gemm<3,128>, cudaFuncAttributeMaxDynamicSharedMemorySize, SM128);
    cudaFuncSetAttribute(mma_gemm<5,128>, cudaFuncAttributeMaxDynamicSharedMemorySize, SM128);
    cudaFuncSetAttribute(mma_gemm<6,128>, cudaFuncAttributeMaxDynamicSharedMemorySize, SM128);
    cudaFuncSetAttribute(mma_gemm<4,64>,  cudaFuncAttributeMaxDynamicSharedMemorySize, SM64);

    // prep: split inputs
    split_rows<<<(3072 * CP + 255) / 256, 256>>>(x, d_xs_h, d_xs_l, (size_t)3072 * CP);
    split_T<<<dim3(HK / 32, Cdim / 32, 1), 256>>>(Wq, d_wq_h, d_wq_l, Cdim, HK, 0, 0);
    split_T<<<dim3(HK / 32, Cdim / 32, 1), 256>>>(Wk, d_wk_h, d_wk_l, Cdim, HK, 0, 0);
    split_T<<<dim3(HV / 32, Cdim / 32, 1), 256>>>(Wv, d_wv_h, d_wv_l, Cdim, HV, 0, 0);
    split_T<<<dim3(HV / 32, HV / 32, 1), 256>>>(Wo, d_wo_h, d_wo_l, HV, HV, 0, 0);
    rk_kernel<<<L2, 256>>>(Wr);

    // fused Q+K projection (N = 1024 over [Wq|Wk])
    mma_gemm<0,128><<<dim3(8, 24, 1), 256, SM128>>>(rwb, rrb, nullptr);
    // V projection
    mma_gemm<2,128><<<dim3(12, 24, 1), 256, SM128>>>(nullptr, nullptr, nullptr);

    // V repack: [z][t][v] -> [z][v][tpair]
    split_T<<<dim3(Vdim / 32, Tdim / 32, ZN), 256>>>(d_gv, d_vt_h, d_vt_l, Tdim, Vdim,
                                                     (size_t)Tdim * Vdim, (size_t)Vdim * CP);

    // logits
    mma_gemm<5,128><<<dim3(12, 12, ZN), 256, SM128>>>(nullptr, nullptr, nullptr);
    mma_gemm<6,128><<<dim3(13, 12, ZN), 256, SM128>>>(nullptr, nullptr, nullptr);

    softmax_kernel<<<ZN * Tdim, 128>>>();

    // P @ V
    mma_gemm<4,64><<<dim3(3, 12, ZN), 256, SM64>>>(nullptr, nullptr, nullptr);

    // out proj
    mma_gemm<3,128><<<dim3(12, 24, 1), 256, SM128>>>(bo, nullptr, out);
}

// round 9
// speedup vs baseline: 1.2110x; 1.2110x over previous
#include <cuda_runtime.h>
#include <cuda_bf16.h>
#include <stdint.h>
#include <math.h>

// Problem constants
#define Bdim 2
#define Tdim 1536
#define Cdim 1536
#define Hdim 8
#define Kdim 64
#define Vdim 192
#define HK   512
#define HV   1536
#define L2   3071     // 2*T-1
#define ZN   16       // B*H
#define CP   768      // 1536/2 pairs
#define KP   32       // 64/2 pairs

// ---------------- scratch ----------------
__device__ uint32_t xs_h[(size_t)3072 * CP],  xs_l[(size_t)3072 * CP];
__device__ uint32_t wq_h[(size_t)HK * CP],    wq_l[(size_t)HK * CP];
__device__ uint32_t wk_h[(size_t)HK * CP],    wk_l[(size_t)HK * CP];
__device__ uint32_t qw_h[(size_t)ZN * Tdim * KP], qw_l[(size_t)ZN * Tdim * KP];
__device__ uint32_t qr_h[(size_t)ZN * Tdim * KP], qr_l[(size_t)ZN * Tdim * KP];
__device__ uint32_t kk_h[(size_t)ZN * Tdim * KP], kk_l[(size_t)ZN * Tdim * KP];
__device__ uint32_t rk_h[(size_t)Hdim * L2 * KP], rk_l[(size_t)Hdim * L2 * KP];
__device__ float    g_v [(size_t)ZN * Tdim * Vdim];
__device__ float    g_logits[(size_t)ZN * Tdim * Tdim];
__device__ float    g_attn[(size_t)3072 * HV];

// ---------------- helpers ----------------
__device__ __forceinline__ uint32_t pack2(float a, float b) {
    uint32_t r;
    asm("cvt.rn.bf16x2.f32 %0, %1, %2;" : "=r"(r) : "f"(b), "f"(a));
    return r;
}
__device__ __forceinline__ void split2(float x0, float x1, uint32_t& h, uint32_t& l) {
    float h0 = __bfloat162float(__float2bfloat16(x0));
    float h1 = __bfloat162float(__float2bfloat16(x1));
    h = pack2(h0, h1);
    l = pack2(x0 - h0, x1 - h1);
}
__device__ __forceinline__ void mma_bf16(float* d, const uint32_t* a, const uint32_t* b) {
    asm volatile(
        "mma.sync.aligned.m16n8k16.row.col.f32.bf16.bf16.f32 "
        "{%0,%1,%2,%3}, {%4,%5,%6,%7}, {%8,%9}, {%0,%1,%2,%3};"
        : "+f"(d[0]), "+f"(d[1]), "+f"(d[2]), "+f"(d[3])
        : "r"(a[0]), "r"(a[1]), "r"(a[2]), "r"(a[3]), "r"(b[0]), "r"(b[1]));
}
__device__ __forceinline__ uint32_t f2tf32(float x) {
    uint32_t r;
    asm("cvt.rna.tf32.f32 %0, %1;" : "=r"(r) : "f"(x));
    return r;
}
__device__ __forceinline__ void mma_tf32(float* d, const uint32_t* a, const uint32_t* b) {
    asm volatile(
        "mma.sync.aligned.m16n8k8.row.col.f32.tf32.tf32.f32 "
        "{%0,%1,%2,%3}, {%4,%5,%6,%7}, {%8,%9}, {%0,%1,%2,%3};"
        : "+f"(d[0]), "+f"(d[1]), "+f"(d[2]), "+f"(d[3])
        : "r"(a[0]), "r"(a[1]), "r"(a[2]), "r"(a[3]), "r"(b[0]), "r"(b[1]));
}
__device__ __forceinline__ void cpa16(uint32_t dst, const void* src) {
    asm volatile("cp.async.cg.shared.global [%0], [%1], 16;" :: "r"(dst), "l"(src));
}
#define CP_COMMIT() asm volatile("cp.async.commit_group;")
__device__ __forceinline__ void ldm4(uint32_t* r, uint32_t addr) {
    asm volatile("ldmatrix.sync.aligned.m8n8.x4.shared.b16 {%0,%1,%2,%3}, [%4];"
                 : "=r"(r[0]), "=r"(r[1]), "=r"(r[2]), "=r"(r[3]) : "r"(addr));
}

// =============== bf16x3 GEMM: 128x64 tile, k-chunk 32, 3-stage, 1 barrier/chunk ===
// MODE 0: x@[Wq|Wk] -> qw,qr,kk | 5: qw@k^T -> logits | 6: qr@rk^T banded scatter-add
#define AROWB 80
#define A_LO  10240
#define B_OFF 20480
#define B_LO  5120
#define STG   30720
#define SMEM_REQ (3 * STG)

template <int MODE>
__global__ __launch_bounds__(256) void mma_gemm(
    const float* __restrict__ bias0, const float* __restrict__ bias1)
{
    extern __shared__ uint8_t dsm[];

    const int z   = blockIdx.z;
    const int m0  = blockIdx.y * 128;
    const int n0  = blockIdx.x * 64;
    const int tid = threadIdx.x;
    const int lane = tid & 31, warp = tid >> 5;
    const int wm = warp >> 1, wn = warp & 1;

    const uint32_t *Ah_g, *Al_g, *Bh_g, *Bl_g;
    int ldpA, ldpB, nchunks;
    bool isQ = true;
    int n0b = n0;
    if (MODE == 0) {
        Ah_g = xs_h; Al_g = xs_l;
        isQ = (n0 < HK);
        if (isQ) { Bh_g = wq_h; Bl_g = wq_l; }
        else     { Bh_g = wk_h; Bl_g = wk_l; n0b = n0 - HK; }
        ldpA = CP; ldpB = CP; nchunks = Cdim / 32;
    }
    else if (MODE == 5) { Ah_g = qw_h + (size_t)z * Tdim * KP; Al_g = qw_l + (size_t)z * Tdim * KP;
                          Bh_g = kk_h + (size_t)z * Tdim * KP; Bl_g = kk_l + (size_t)z * Tdim * KP;
                          ldpA = KP; ldpB = KP; nchunks = Kdim / 32; }
    else                { Ah_g = qr_h + (size_t)z * Tdim * KP; Al_g = qr_l + (size_t)z * Tdim * KP;
                          Bh_g = rk_h + (size_t)(z & 7) * L2 * KP; Bl_g = rk_l + (size_t)(z & 7) * L2 * KP;
                          ldpA = KP; ldpB = KP; nchunks = Kdim / 32; }

    const int cb = (MODE == 6) ? (1408 - m0 + n0) : n0b;

    const uint32_t sb = (uint32_t)__cvta_generic_to_shared(dsm);

    // ---- producer assignments ----
    const int ar = tid >> 1, ac2 = (tid & 1) * 2;
    const int br = tid >> 2, bc  = tid & 3;
    int bgr = cb + br;
    if (MODE == 6 && bgr > L2 - 1) bgr = L2 - 1;
    const size_t aoff0 = (size_t)(m0 + ar) * ldpA + ac2 * 4;
    const size_t boff0 = (size_t)bgr * ldpB + bc * 4;
    const uint32_t adst0 = sb + ar * AROWB + ac2 * 16;
    const uint32_t bdst0 = sb + B_OFF + br * AROWB + bc * 16;

    auto fill = [&](int s, int c) {
        const uint32_t st = s * STG;
        const size_t ko = (size_t)c * 16;
        cpa16(adst0 + st,             Ah_g + aoff0 + ko);
        cpa16(adst0 + st + 16,        Ah_g + aoff0 + ko + 4);
        cpa16(adst0 + st + A_LO,      Al_g + aoff0 + ko);
        cpa16(adst0 + st + A_LO + 16, Al_g + aoff0 + ko + 4);
        cpa16(bdst0 + st,             Bh_g + boff0 + ko);
        cpa16(bdst0 + st + B_LO,      Bl_g + boff0 + ko);
        CP_COMMIT();
    };

    // ---- consumer lane addressing ----
    const int mat = lane >> 3, rIn = lane & 7;
    const int mrow = (mat & 1) * 8 + rIn;
    const int colb = (mat >> 1) * 16;
    const uint32_t aAddr = sb + (uint32_t)((wm * 32 + mrow) * AROWB + colb);
    const uint32_t bAddr = sb + (uint32_t)(B_OFF + (wn * 32 + mrow) * AROWB + colb);

    float acc[2][4][4] = {};

    fill(0, 0);
    if (nchunks > 1) fill(1, 1);

    for (int c = 0; c < nchunks; c++) {
        const int s = c % 3;
        if (c + 1 < nchunks) asm volatile("cp.async.wait_group 1;");
        else                 asm volatile("cp.async.wait_group 0;");
        __syncthreads();
        if (c + 2 < nchunks) fill((c + 2) % 3, c + 2);

        const uint32_t st = s * STG;
        #pragma unroll
        for (int kh = 0; kh < 2; kh++) {
            uint32_t ah[2][4], al[2][4], bh[2][4], bl[2][4];
            ldm4(ah[0], aAddr + st + kh * 32);
            ldm4(ah[1], aAddr + st + 16 * AROWB + kh * 32);
            ldm4(al[0], aAddr + st + A_LO + kh * 32);
            ldm4(al[1], aAddr + st + A_LO + 16 * AROWB + kh * 32);
            ldm4(bh[0], bAddr + st + kh * 32);
            ldm4(bh[1], bAddr + st + 16 * AROWB + kh * 32);
            ldm4(bl[0], bAddr + st + B_LO + kh * 32);
            ldm4(bl[1], bAddr + st + B_LO + 16 * AROWB + kh * 32);
            #pragma unroll
            for (int mi = 0; mi < 2; mi++)
                #pragma unroll
                for (int ni = 0; ni < 4; ni++) {
                    const int ng = ni >> 1, j = ni & 1;
                    uint32_t b2h[2] = { bh[ng][j], bh[ng][j + 2] };
                    uint32_t b2l[2] = { bl[ng][j], bl[ng][j + 2] };
                    mma_bf16(acc[mi][ni], ah[mi], b2h);
                    mma_bf16(acc[mi][ni], ah[mi], b2l);
                    mma_bf16(acc[mi][ni], al[mi], b2h);
                }
        }
    }

    // ---------------- epilogue ----------------
    #pragma unroll
    for (int mi = 0; mi < 2; mi++) {
        #pragma unroll
        for (int ni = 0; ni < 4; ni++) {
            #pragma unroll
            for (int hh = 0; hh < 2; hh++) {
                const int row = m0 + wm * 32 + mi * 16 + (lane >> 2) + hh * 8;
                const int col = cb + wn * 32 + ni * 8 + 2 * (lane & 3);
                float v0 = acc[mi][ni][hh * 2 + 0];
                float v1 = acc[mi][ni][hh * 2 + 1];

                if (MODE == 0) {
                    int bb = row / Tdim, t = row % Tdim;
                    int h = col >> 6, kw = col & 63;
                    size_t idx = (((size_t)(bb * Hdim + h)) * Tdim + t) * KP + (kw >> 1);
                    if (isQ) {
                        float q0 = v0 * 0.125f, q1 = v1 * 0.125f;
                        uint32_t hw, lw;
                        split2(q0 + bias0[col], q1 + bias0[col + 1], hw, lw);
                        qw_h[idx] = hw; qw_l[idx] = lw;
                        split2(q0 + bias1[col], q1 + bias1[col + 1], hw, lw);
                        qr_h[idx] = hw; qr_l[idx] = lw;
                    } else {
                        uint32_t hw, lw;
                        split2(v0, v1, hw, lw);
                        kk_h[idx] = hw; kk_l[idx] = lw;
                    }
                } else if (MODE == 5) {
                    *(float2*)&g_logits[((size_t)z * Tdim + row) * Tdim + col] = make_float2(v0, v1);
                } else { // MODE 6 scatter-add: s = r + t - (T-1)
                    float* pl = g_logits + ((size_t)z * Tdim + row) * Tdim;
                    int s0 = col + row - (Tdim - 1);
                    if (s0 >= 0 && s0 < Tdim) pl[s0] += v0;
                    if (s0 + 1 >= 0 && s0 + 1 < Tdim) pl[s0 + 1] += v1;
                }
            }
        }
    }
}

// =============== tf32 single-pass GEMM (downstream, error-tolerant) ==============
// MODE 2: x@Wv -> g_v | 3: attn@Wo + bo -> out | 4: P@V -> g_attn
template <int MODE>
__global__ __launch_bounds__(256) void tf32_gemm(
    const float* __restrict__ Aext, const float* __restrict__ Bext,
    const float* __restrict__ bias0, float* __restrict__ outp,
    int Kc, int lda, int ldb)
{
    __shared__ uint32_t As[128 * 20];
    __shared__ uint32_t Bs[16 * 72];

    const int z   = blockIdx.z;
    const int m0  = blockIdx.y * 128;
    const int n0  = blockIdx.x * 64;
    const int tid = threadIdx.x;
    const int lane = tid & 31, warp = tid >> 5;
    const int wm = warp >> 1, wn = warp & 1;

    const float* Ap;
    const float* Bp;
    if (MODE == 4)      { Ap = g_logits + (size_t)z * Tdim * Tdim; Bp = g_v + (size_t)z * Tdim * Vdim; }
    else if (MODE == 3) { Ap = g_attn; Bp = Bext; }
    else                { Ap = Aext; Bp = Bext; }

    float acc[2][4][4] = {};

    for (int kc = 0; kc < Kc; kc += 16) {
        #pragma unroll
        for (int it = 0; it < 2; it++) {
            int idx = tid + it * 256;
            int row = idx >> 2, q = idx & 3;
            float4 v = *(const float4*)(Ap + (size_t)(m0 + row) * lda + kc + q * 4);
            uint4 u = make_uint4(f2tf32(v.x), f2tf32(v.y), f2tf32(v.z), f2tf32(v.w));
            *(uint4*)&As[row * 20 + q * 4] = u;
        }
        {
            int row = tid >> 4, q = tid & 15;
            float4 v = *(const float4*)(Bp + (size_t)(kc + row) * ldb + n0 + q * 4);
            uint4 u = make_uint4(f2tf32(v.x), f2tf32(v.y), f2tf32(v.z), f2tf32(v.w));
            *(uint4*)&Bs[row * 72 + q * 4] = u;
        }
        __syncthreads();

        #pragma unroll
        for (int ks = 0; ks < 2; ks++) {
            const int kb = ks * 8 + (lane & 3);
            uint32_t a[2][4], b[4][2];
            const int ar0 = wm * 32 + (lane >> 2);
            #pragma unroll
            for (int mi = 0; mi < 2; mi++) {
                int r = ar0 + mi * 16;
                a[mi][0] = As[r * 20 + kb];
                a[mi][1] = As[(r + 8) * 20 + kb];
                a[mi][2] = As[r * 20 + kb + 4];
                a[mi][3] = As[(r + 8) * 20 + kb + 4];
            }
            #pragma unroll
            for (int ni = 0; ni < 4; ni++) {
                int n = wn * 32 + ni * 8 + (lane >> 2);
                b[ni][0] = Bs[kb * 72 + n];
                b[ni][1] = Bs[(kb + 4) * 72 + n];
            }
            #pragma unroll
            for (int mi = 0; mi < 2; mi++)
                #pragma unroll
                for (int ni = 0; ni < 4; ni++)
                    mma_tf32(acc[mi][ni], a[mi], b[ni]);
        }
        __syncthreads();
    }

    #pragma unroll
    for (int mi = 0; mi < 2; mi++) {
        #pragma unroll
        for (int ni = 0; ni < 4; ni++) {
            #pragma unroll
            for (int hh = 0; hh < 2; hh++) {
                const int row = m0 + wm * 32 + mi * 16 + (lane >> 2) + hh * 8;
                const int col = n0 + wn * 32 + ni * 8 + 2 * (lane & 3);
                float v0 = acc[mi][ni][hh * 2 + 0];
                float v1 = acc[mi][ni][hh * 2 + 1];

                if (MODE == 2) {
                    int bb = row / Tdim, t = row % Tdim;
                    int h = col / Vdim, vv = col % Vdim;
                    *(float2*)&g_v[(((size_t)(bb * Hdim + h)) * Tdim + t) * Vdim + vv] = make_float2(v0, v1);
                } else if (MODE == 3) {
                    *(float2*)&outp[(size_t)row * HV + col] = make_float2(v0 + bias0[col], v1 + bias0[col + 1]);
                } else { // MODE 4
                    int bb = z >> 3, h = z & 7;
                    *(float2*)&g_attn[((size_t)(bb * Tdim + row)) * HV + h * Vdim + col] = make_float2(v0, v1);
                }
            }
        }
    }
}

// ---------------- prep kernels ----------------
__global__ void split_rows(const float* __restrict__ in, uint32_t* __restrict__ oh,
                           uint32_t* __restrict__ ol, size_t npairs)
{
    size_t i = (size_t)blockIdx.x * blockDim.x + threadIdx.x;
    if (i >= npairs) return;
    float2 v = ((const float2*)in)[i];
    split2(v.x, v.y, oh[i], ol[i]);
}

__global__ void split_T(const float* __restrict__ in, uint32_t* __restrict__ oh,
                        uint32_t* __restrict__ ol, int Kc, int N)
{
    __shared__ float tile[32][33];
    int k0 = blockIdx.y * 32, n0 = blockIdx.x * 32;
    int tid = threadIdx.x;
    #pragma unroll
    for (int i = 0; i < 4; i++) {
        int idx = tid + i * 256;
        int kr = idx >> 5, nn = idx & 31;
        tile[kr][nn] = in[(size_t)(k0 + kr) * N + n0 + nn];
    }
    __syncthreads();
    #pragma unroll
    for (int i = 0; i < 2; i++) {
        int idx = tid + i * 256;
        int nn = idx >> 4, kp = idx & 15;
        uint32_t h, l;
        split2(tile[2 * kp][nn], tile[2 * kp + 1][nn], h, l);
        size_t o = (size_t)(n0 + nn) * (Kc / 2) + k0 / 2 + kp;
        oh[o] = h; ol[o] = l;
    }
}

__global__ void rk_kernel(const float* __restrict__ Wr)
{
    __shared__ float cw[16];
    int r = blockIdx.x;
    int tid = threadIdx.x;
    if (tid < 16) {
        float pr = (float)exp(log((double)(Tdim + 1)) / 16.0);
        cw[tid] = powf(pr, (float)(tid + 1)) - 1.0f;
    }
    __syncthreads();
    float d  = (float)(r - (Tdim - 1));
    float ad = fabsf(d);
    float sg = (d > 0.f) ? 1.f : ((d < 0.f) ? -1.f : 0.f);
    int h = tid >> 5, kp = tid & 31;
    int c0 = h * 64 + 2 * kp;
    float a0 = 0.f, a1 = 0.f;
    #pragma unroll
    for (int i = 0; i < 16; i++)
        if (cw[i] > ad) {
            a0 += Wr[i * HK + c0]     + sg * Wr[(i + 16) * HK + c0];
            a1 += Wr[i * HK + c0 + 1] + sg * Wr[(i + 16) * HK + c0 + 1];
        }
    uint32_t hw, lw;
    split2(a0, a1, hw, lw);
    size_t idx = ((size_t)h * L2 + r) * KP + kp;
    rk_h[idx] = hw; rk_l[idx] = lw;
}

// ---------------- row softmax, in-place fp32 on g_logits --------------------------
__global__ void softmax_kernel()
{
    const size_t row = blockIdx.x;
    float4* p = (float4*)(g_logits + row * Tdim);
    const int tid = threadIdx.x;     // 128 threads, 3 float4 each
    __shared__ float red[4];

    float4 v[3];
    float m = -1e30f;
    #pragma unroll
    for (int e = 0; e < 3; e++) {
        v[e] = p[tid + e * 128];
        m = fmaxf(m, fmaxf(fmaxf(v[e].x, v[e].y), fmaxf(v[e].z, v[e].w)));
    }
    #pragma unroll
    for (int o = 16; o > 0; o >>= 1) m = fmaxf(m, __shfl_xor_sync(0xffffffffu, m, o));
    if ((tid & 31) == 0) red[tid >> 5] = m;
    __syncthreads();
    m = fmaxf(fmaxf(red[0], red[1]), fmaxf(red[2], red[3]));
    __syncthreads();

    float s = 0.f;
    #pragma unroll
    for (int e = 0; e < 3; e++) {
        v[e].x = __expf(v[e].x - m); v[e].y = __expf(v[e].y - m);
        v[e].z = __expf(v[e].z - m); v[e].w = __expf(v[e].w - m);
        s += v[e].x + v[e].y + v[e].z + v[e].w;
    }
    #pragma unroll
    for (int o = 16; o > 0; o >>= 1) s += __shfl_xor_sync(0xffffffffu, s, o);
    if ((tid & 31) == 0) red[tid >> 5] = s;
    __syncthreads();
    s = red[0] + red[1] + red[2] + red[3];
    float inv = 1.0f / s;
    #pragma unroll
    for (int e = 0; e < 3; e++) {
        v[e].x *= inv; v[e].y *= inv; v[e].z *= inv; v[e].w *= inv;
        p[tid + e * 128] = v[e];
    }
}

// ---------------- launch ----------------------------------------------------------
extern "C" void kernel_launch(void* const* d_in, const int* in_sizes, int n_in,
                              void* d_out, int out_size)
{
    const float* x   = (const float*)d_in[0];
    const float* Wq  = (const float*)d_in[1];
    const float* Wk  = (const float*)d_in[2];
    const float* Wv  = (const float*)d_in[3];
    const float* Wr  = (const float*)d_in[4];
    const float* rwb = (const float*)d_in[5];
    const float* rrb = (const float*)d_in[6];
    const float* Wo  = (const float*)d_in[7];
    const float* bo  = (const float*)d_in[8];
    float* out = (float*)d_out;

    uint32_t *d_xs_h, *d_xs_l, *d_wq_h, *d_wq_l, *d_wk_h, *d_wk_l;
    cudaGetSymbolAddress((void**)&d_xs_h, xs_h); cudaGetSymbolAddress((void**)&d_xs_l, xs_l);
    cudaGetSymbolAddress((void**)&d_wq_h, wq_h); cudaGetSymbolAddress((void**)&d_wq_l, wq_l);
    cudaGetSymbolAddress((void**)&d_wk_h, wk_h); cudaGetSymbolAddress((void**)&d_wk_l, wk_l);

    cudaFuncSetAttribute(mma_gemm<0>, cudaFuncAttributeMaxDynamicSharedMemorySize, SMEM_REQ);
    cudaFuncSetAttribute(mma_gemm<5>, cudaFuncAttributeMaxDynamicSharedMemorySize, SMEM_REQ);
    cudaFuncSetAttribute(mma_gemm<6>, cudaFuncAttributeMaxDynamicSharedMemorySize, SMEM_REQ);

    // prep: split inputs for bf16x3 path
    split_rows<<<(3072 * CP + 255) / 256, 256>>>(x, d_xs_h, d_xs_l, (size_t)3072 * CP);
    split_T<<<dim3(HK / 32, Cdim / 32, 1), 256>>>(Wq, d_wq_h, d_wq_l, Cdim, HK);
    split_T<<<dim3(HK / 32, Cdim / 32, 1), 256>>>(Wk, d_wk_h, d_wk_l, Cdim, HK);
    rk_kernel<<<L2, 256>>>(Wr);

    // fused Q+K projection (bf16x3, precision-critical)
    mma_gemm<0><<<dim3(16, 24, 1), 256, SMEM_REQ>>>(rwb, rrb);
    // V projection (tf32 single-pass)
    tf32_gemm<2><<<dim3(HV / 64, 24, 1), 256>>>(x, Wv, nullptr, nullptr, Cdim, Cdim, HV);

    // logits (bf16x3, precision-critical)
    mma_gemm<5><<<dim3(24, 12, ZN), 256, SMEM_REQ>>>(nullptr, nullptr);
    mma_gemm<6><<<dim3(26, 12, ZN), 256, SMEM_REQ>>>(nullptr, nullptr);

    softmax_kernel<<<ZN * Tdim, 128>>>();

    // P @ V (tf32 single-pass)
    tf32_gemm<4><<<dim3(Vdim / 64, 12, ZN), 256>>>(nullptr, nullptr, nullptr, nullptr, Tdim, Tdim, Vdim);

    // out proj (tf32 single-pass)
    tf32_gemm<3><<<dim3(HV / 64, 24, 1), 256>>>(nullptr, Wo, bo, out, HV, HV, HV);
}

// round 10
// speedup vs baseline: 1.3910x; 1.1486x over previous
#include <cuda_runtime.h>
#include <cuda_bf16.h>
#include <stdint.h>
#include <math.h>

// Problem constants
#define Bdim 2
#define Tdim 1536
#define Cdim 1536
#define Hdim 8
#define Kdim 64
#define Vdim 192
#define HK   512
#define HV   1536
#define ZN   16       // B*H
#define CP   768      // 1536/2 pairs
#define KP   32       // 64/2 pairs

// ---------------- scratch ----------------
__device__ uint32_t xs_h[(size_t)3072 * CP],  xs_l[(size_t)3072 * CP];
__device__ uint32_t wq_h[(size_t)HK * CP],    wq_l[(size_t)HK * CP];
__device__ uint32_t wk_h[(size_t)HK * CP],    wk_l[(size_t)HK * CP];
__device__ uint32_t qw_h[(size_t)ZN * Tdim * KP], qw_l[(size_t)ZN * Tdim * KP];
__device__ uint32_t kk_h[(size_t)ZN * Tdim * KP], kk_l[(size_t)ZN * Tdim * KP];
__device__ float    g_qrf[(size_t)ZN * Tdim * Kdim];          // fp32 qr (for u)
__device__ float    g_S1[(size_t)ZN * Tdim * 20];             // suffix sums (17 used)
__device__ float    g_S2[(size_t)ZN * Tdim * 20];
__device__ float    g_v [(size_t)ZN * Tdim * Vdim];
__device__ float    g_logits[(size_t)ZN * Tdim * Tdim];
__device__ float    g_attn[(size_t)3072 * HV];

// ---------------- helpers ----------------
__device__ __forceinline__ uint32_t pack2(float a, float b) {
    uint32_t r;
    asm("cvt.rn.bf16x2.f32 %0, %1, %2;" : "=r"(r) : "f"(b), "f"(a));
    return r;
}
__device__ __forceinline__ void split2(float x0, float x1, uint32_t& h, uint32_t& l) {
    float h0 = __bfloat162float(__float2bfloat16(x0));
    float h1 = __bfloat162float(__float2bfloat16(x1));
    h = pack2(h0, h1);
    l = pack2(x0 - h0, x1 - h1);
}
__device__ __forceinline__ void mma_bf16(float* d, const uint32_t* a, const uint32_t* b) {
    asm volatile(
        "mma.sync.aligned.m16n8k16.row.col.f32.bf16.bf16.f32 "
        "{%0,%1,%2,%3}, {%4,%5,%6,%7}, {%8,%9}, {%0,%1,%2,%3};"
        : "+f"(d[0]), "+f"(d[1]), "+f"(d[2]), "+f"(d[3])
        : "r"(a[0]), "r"(a[1]), "r"(a[2]), "r"(a[3]), "r"(b[0]), "r"(b[1]));
}
__device__ __forceinline__ uint32_t f2tf32(float x) {
    uint32_t r;
    asm("cvt.rna.tf32.f32 %0, %1;" : "=r"(r) : "f"(x));
    return r;
}
__device__ __forceinline__ void mma_tf32(float* d, const uint32_t* a, const uint32_t* b) {
    asm volatile(
        "mma.sync.aligned.m16n8k8.row.col.f32.tf32.tf32.f32 "
        "{%0,%1,%2,%3}, {%4,%5,%6,%7}, {%8,%9}, {%0,%1,%2,%3};"
        : "+f"(d[0]), "+f"(d[1]), "+f"(d[2]), "+f"(d[3])
        : "r"(a[0]), "r"(a[1]), "r"(a[2]), "r"(a[3]), "r"(b[0]), "r"(b[1]));
}
__device__ __forceinline__ void cpa16(uint32_t dst, const void* src) {
    asm volatile("cp.async.cg.shared.global [%0], [%1], 16;" :: "r"(dst), "l"(src));
}
#define CP_COMMIT() asm volatile("cp.async.commit_group;")
__device__ __forceinline__ void ldm4(uint32_t* r, uint32_t addr) {
    asm volatile("ldmatrix.sync.aligned.m8n8.x4.shared.b16 {%0,%1,%2,%3}, [%4];"
                 : "=r"(r[0]), "=r"(r[1]), "=r"(r[2]), "=r"(r[3]) : "r"(addr));
}

// =============== bf16x3 GEMM: 128x64 tile, k-chunk 32, 3-stage, 1 barrier/chunk ===
// MODE 0: x@[Wq|Wk] -> qw(split)+qr(f32), kk(split) | 5: qw@k^T -> logits
#define AROWB 80
#define A_LO  10240
#define B_OFF 20480
#define B_LO  5120
#define STG   30720
#define SMEM_REQ (3 * STG)

template <int MODE>
__global__ __launch_bounds__(256) void mma_gemm(
    const float* __restrict__ bias0, const float* __restrict__ bias1)
{
    extern __shared__ uint8_t dsm[];

    const int z   = blockIdx.z;
    const int m0  = blockIdx.y * 128;
    const int n0  = blockIdx.x * 64;
    const int tid = threadIdx.x;
    const int lane = tid & 31, warp = tid >> 5;
    const int wm = warp >> 1, wn = warp & 1;

    const uint32_t *Ah_g, *Al_g, *Bh_g, *Bl_g;
    int ldpA, ldpB, nchunks;
    bool isQ = true;
    int n0b = n0;
    if (MODE == 0) {
        Ah_g = xs_h; Al_g = xs_l;
        isQ = (n0 < HK);
        if (isQ) { Bh_g = wq_h; Bl_g = wq_l; }
        else     { Bh_g = wk_h; Bl_g = wk_l; n0b = n0 - HK; }
        ldpA = CP; ldpB = CP; nchunks = Cdim / 32;
    } else {
        Ah_g = qw_h + (size_t)z * Tdim * KP; Al_g = qw_l + (size_t)z * Tdim * KP;
        Bh_g = kk_h + (size_t)z * Tdim * KP; Bl_g = kk_l + (size_t)z * Tdim * KP;
        ldpA = KP; ldpB = KP; nchunks = Kdim / 32;
    }

    const int cb = n0b;

    const uint32_t sb = (uint32_t)__cvta_generic_to_shared(dsm);

    const int ar = tid >> 1, ac2 = (tid & 1) * 2;
    const int br = tid >> 2, bc  = tid & 3;
    const size_t aoff0 = (size_t)(m0 + ar) * ldpA + ac2 * 4;
    const size_t boff0 = (size_t)(cb + br) * ldpB + bc * 4;
    const uint32_t adst0 = sb + ar * AROWB + ac2 * 16;
    const uint32_t bdst0 = sb + B_OFF + br * AROWB + bc * 16;

    auto fill = [&](int s, int c) {
        const uint32_t st = s * STG;
        const size_t ko = (size_t)c * 16;
        cpa16(adst0 + st,             Ah_g + aoff0 + ko);
        cpa16(adst0 + st + 16,        Ah_g + aoff0 + ko + 4);
        cpa16(adst0 + st + A_LO,      Al_g + aoff0 + ko);
        cpa16(adst0 + st + A_LO + 16, Al_g + aoff0 + ko + 4);
        cpa16(bdst0 + st,             Bh_g + boff0 + ko);
        cpa16(bdst0 + st + B_LO,      Bl_g + boff0 + ko);
        CP_COMMIT();
    };

    const int mat = lane >> 3, rIn = lane & 7;
    const int mrow = (mat & 1) * 8 + rIn;
    const int colb = (mat >> 1) * 16;
    const uint32_t aAddr = sb + (uint32_t)((wm * 32 + mrow) * AROWB + colb);
    const uint32_t bAddr = sb + (uint32_t)(B_OFF + (wn * 32 + mrow) * AROWB + colb);

    float acc[2][4][4] = {};

    fill(0, 0);
    if (nchunks > 1) fill(1, 1);

    for (int c = 0; c < nchunks; c++) {
        const int s = c % 3;
        if (c + 1 < nchunks) asm volatile("cp.async.wait_group 1;");
        else                 asm volatile("cp.async.wait_group 0;");
        __syncthreads();
        if (c + 2 < nchunks) fill((c + 2) % 3, c + 2);

        const uint32_t st = s * STG;
        #pragma unroll
        for (int kh = 0; kh < 2; kh++) {
            uint32_t ah[2][4], al[2][4], bh[2][4], bl[2][4];
            ldm4(ah[0], aAddr + st + kh * 32);
            ldm4(ah[1], aAddr + st + 16 * AROWB + kh * 32);
            ldm4(al[0], aAddr + st + A_LO + kh * 32);
            ldm4(al[1], aAddr + st + A_LO + 16 * AROWB + kh * 32);
            ldm4(bh[0], bAddr + st + kh * 32);
            ldm4(bh[1], bAddr + st + 16 * AROWB + kh * 32);
            ldm4(bl[0], bAddr + st + B_LO + kh * 32);
            ldm4(bl[1], bAddr + st + B_LO + 16 * AROWB + kh * 32);
            #pragma unroll
            for (int mi = 0; mi < 2; mi++)
                #pragma unroll
                for (int ni = 0; ni < 4; ni++) {
                    const int ng = ni >> 1, j = ni & 1;
                    uint32_t b2h[2] = { bh[ng][j], bh[ng][j + 2] };
                    uint32_t b2l[2] = { bl[ng][j], bl[ng][j + 2] };
                    mma_bf16(acc[mi][ni], ah[mi], b2h);
                    mma_bf16(acc[mi][ni], ah[mi], b2l);
                    mma_bf16(acc[mi][ni], al[mi], b2h);
                }
        }
    }

    // ---------------- epilogue ----------------
    #pragma unroll
    for (int mi = 0; mi < 2; mi++) {
        #pragma unroll
        for (int ni = 0; ni < 4; ni++) {
            #pragma unroll
            for (int hh = 0; hh < 2; hh++) {
                const int row = m0 + wm * 32 + mi * 16 + (lane >> 2) + hh * 8;
                const int col = cb + wn * 32 + ni * 8 + 2 * (lane & 3);
                float v0 = acc[mi][ni][hh * 2 + 0];
                float v1 = acc[mi][ni][hh * 2 + 1];

                if (MODE == 0) {
                    int bb = row / Tdim, t = row % Tdim;
                    int h = col >> 6, kw = col & 63;
                    size_t idx = (((size_t)(bb * Hdim + h)) * Tdim + t) * KP + (kw >> 1);
                    if (isQ) {
                        float q0 = v0 * 0.125f, q1 = v1 * 0.125f;
                        uint32_t hw, lw;
                        split2(q0 + bias0[col], q1 + bias0[col + 1], hw, lw);
                        qw_h[idx] = hw; qw_l[idx] = lw;
                        // qr in fp32 for the rank-32 rel path
                        *(float2*)&g_qrf[(((size_t)(bb * Hdim + h)) * Tdim + t) * Kdim + kw] =
                            make_float2(q0 + bias1[col], q1 + bias1[col + 1]);
                    } else {
                        uint32_t hw, lw;
                        split2(v0, v1, hw, lw);
                        kk_h[idx] = hw; kk_l[idx] = lw;
                    }
                } else {
                    *(float2*)&g_logits[((size_t)z * Tdim + row) * Tdim + col] = make_float2(v0, v1);
                }
            }
        }
    }
}

// =============== tf32 single-pass GEMM (downstream, error-tolerant) ==============
// MODE 2: x@Wv -> g_v | 3: attn@Wo + bo -> out | 4: P@V -> g_attn
template <int MODE>
__global__ __launch_bounds__(256) void tf32_gemm(
    const float* __restrict__ Aext, const float* __restrict__ Bext,
    const float* __restrict__ bias0, float* __restrict__ outp,
    int Kc, int lda, int ldb)
{
    __shared__ uint32_t As[128 * 20];
    __shared__ uint32_t Bs[16 * 72];

    const int z   = blockIdx.z;
    const int m0  = blockIdx.y * 128;
    const int n0  = blockIdx.x * 64;
    const int tid = threadIdx.x;
    const int lane = tid & 31, warp = tid >> 5;
    const int wm = warp >> 1, wn = warp & 1;

    const float* Ap;
    const float* Bp;
    if (MODE == 4)      { Ap = g_logits + (size_t)z * Tdim * Tdim; Bp = g_v + (size_t)z * Tdim * Vdim; }
    else if (MODE == 3) { Ap = g_attn; Bp = Bext; }
    else                { Ap = Aext; Bp = Bext; }

    float acc[2][4][4] = {};

    for (int kc = 0; kc < Kc; kc += 16) {
        #pragma unroll
        for (int it = 0; it < 2; it++) {
            int idx = tid + it * 256;
            int row = idx >> 2, q = idx & 3;
            float4 v = *(const float4*)(Ap + (size_t)(m0 + row) * lda + kc + q * 4);
            uint4 u = make_uint4(f2tf32(v.x), f2tf32(v.y), f2tf32(v.z), f2tf32(v.w));
            *(uint4*)&As[row * 20 + q * 4] = u;
        }
        {
            int row = tid >> 4, q = tid & 15;
            float4 v = *(const float4*)(Bp + (size_t)(kc + row) * ldb + n0 + q * 4);
            uint4 u = make_uint4(f2tf32(v.x), f2tf32(v.y), f2tf32(v.z), f2tf32(v.w));
            *(uint4*)&Bs[row * 72 + q * 4] = u;
        }
        __syncthreads();

        #pragma unroll
        for (int ks = 0; ks < 2; ks++) {
            const int kb = ks * 8 + (lane & 3);
            uint32_t a[2][4], b[4][2];
            const int ar0 = wm * 32 + (lane >> 2);
            #pragma unroll
            for (int mi = 0; mi < 2; mi++) {
                int r = ar0 + mi * 16;
                a[mi][0] = As[r * 20 + kb];
                a[mi][1] = As[(r + 8) * 20 + kb];
                a[mi][2] = As[r * 20 + kb + 4];
                a[mi][3] = As[(r + 8) * 20 + kb + 4];
            }
            #pragma unroll
            for (int ni = 0; ni < 4; ni++) {
                int n = wn * 32 + ni * 8 + (lane >> 2);
                b[ni][0] = Bs[kb * 72 + n];
                b[ni][1] = Bs[(kb + 4) * 72 + n];
            }
            #pragma unroll
            for (int mi = 0; mi < 2; mi++)
                #pragma unroll
                for (int ni = 0; ni < 4; ni++)
                    mma_tf32(acc[mi][ni], a[mi], b[ni]);
        }
        __syncthreads();
    }

    #pragma unroll
    for (int mi = 0; mi < 2; mi++) {
        #pragma unroll
        for (int ni = 0; ni < 4; ni++) {
            #pragma unroll
            for (int hh = 0; hh < 2; hh++) {
                const int row = m0 + wm * 32 + mi * 16 + (lane >> 2) + hh * 8;
                const int col = n0 + wn * 32 + ni * 8 + 2 * (lane & 3);
                float v0 = acc[mi][ni][hh * 2 + 0];
                float v1 = acc[mi][ni][hh * 2 + 1];

                if (MODE == 2) {
                    int bb = row / Tdim, t = row % Tdim;
                    int h = col / Vdim, vv = col % Vdim;
                    *(float2*)&g_v[(((size_t)(bb * Hdim + h)) * Tdim + t) * Vdim + vv] = make_float2(v0, v1);
                } else if (MODE == 3) {
                    *(float2*)&outp[(size_t)row * HV + col] = make_float2(v0 + bias0[col], v1 + bias0[col + 1]);
                } else { // MODE 4
                    int bb = z >> 3, h = z & 7;
                    *(float2*)&g_attn[((size_t)(bb * Tdim + row)) * HV + h * Vdim + col] = make_float2(v0, v1);
                }
            }
        }
    }
}

// ---------------- prep kernels ----------------
__global__ void split_rows(const float* __restrict__ in, uint32_t* __restrict__ oh,
                           uint32_t* __restrict__ ol, size_t npairs)
{
    size_t i = (size_t)blockIdx.x * blockDim.x + threadIdx.x;
    if (i >= npairs) return;
    float2 v = ((const float2*)in)[i];
    split2(v.x, v.y, oh[i], ol[i]);
}

__global__ void split_T(const float* __restrict__ in, uint32_t* __restrict__ oh,
                        uint32_t* __restrict__ ol, int Kc, int N)
{
    __shared__ float tile[32][33];
    int k0 = blockIdx.y * 32, n0 = blockIdx.x * 32;
    int tid = threadIdx.x;
    #pragma unroll
    for (int i = 0; i < 4; i++) {
        int idx = tid + i * 256;
        int kr = idx >> 5, nn = idx & 31;
        tile[kr][nn] = in[(size_t)(k0 + kr) * N + n0 + nn];
    }
    __syncthreads();
    #pragma unroll
    for (int i = 0; i < 2; i++) {
        int idx = tid + i * 256;
        int nn = idx >> 4, kp = idx & 15;
        uint32_t h, l;
        split2(tile[2 * kp][nn], tile[2 * kp + 1][nn], h, l);
        size_t o = (size_t)(n0 + nn) * (Kc / 2) + k0 / 2 + kp;
        oh[o] = h; ol[o] = l;
    }
}

// ---------------- u + suffix sums: u[t,f] = qr_t · Wr[f,h,:]; S = suffix over f ----
__global__ void u_kernel(const float* __restrict__ Wr)
{
    __shared__ float us[4][32];
    const int warp = threadIdx.x >> 5, lane = threadIdx.x & 31;
    const int rz = blockIdx.x * 4 + warp;           // z*T + t
    const int h = (rz / Tdim) & 7;
    const float* qr = g_qrf + (size_t)rz * Kdim;
    const float q0 = qr[lane], q1 = qr[lane + 32];
    const float* w = Wr + lane * HK + h * 64;       // Wr row f = lane
    float acc = 0.f;
    #pragma unroll
    for (int k = 0; k < 32; k++)
        acc += __shfl_sync(0xffffffffu, q0, k) * w[k];
    #pragma unroll
    for (int k = 0; k < 32; k++)
        acc += __shfl_sync(0xffffffffu, q1, k) * w[k + 32];
    us[warp][lane] = acc;
    __syncwarp();
    if (lane < 17) {
        float s1 = 0.f, s2 = 0.f;
        for (int i = lane; i < 16; i++) { s1 += us[warp][i]; s2 += us[warp][16 + i]; }
        g_S1[(size_t)rz * 20 + lane] = s1;
        g_S2[(size_t)rz * 20 + lane] = s2;
    }
}

// ---------------- softmax with fused rel add (S1/S2 lookup), in-place fp32 -------
__global__ void softmax_kernel()
{
    const int row = blockIdx.x;          // z*T + t
    const int t = row % Tdim;
    float4* p = (float4*)(g_logits + (size_t)row * Tdim);
    const int tid = threadIdx.x;         // 128 threads, 3 float4 each
    __shared__ float red[4];
    __shared__ float cws[16];
    __shared__ float s1s[17], s2s[17];
    __shared__ uint8_t lut[Tdim];

    if (tid < 16)
        cws[tid] = powf((float)exp(log((double)(Tdim + 1)) / 16.0), (float)(tid + 1)) - 1.0f;
    if (tid >= 16 && tid < 33) {
        int j = tid - 16;
        s1s[j] = g_S1[(size_t)row * 20 + j];
        s2s[j] = g_S2[(size_t)row * 20 + j];
    }
    __syncthreads();
    for (int d = tid; d < Tdim; d += 128) {
        float fd = (float)d;
        int j = 0;
        #pragma unroll
        for (int i = 0; i < 16; i++) j += (cws[i] <= fd);
        lut[d] = (uint8_t)j;
    }
    __syncthreads();

    float4 v[3];
    float m = -1e30f;
    #pragma unroll
    for (int e = 0; e < 3; e++) {
        v[e] = p[tid + e * 128];
        const int sbase = (tid + e * 128) * 4;
        float* vc = (float*)&v[e];
        #pragma unroll
        for (int q = 0; q < 4; q++) {
            int d = sbase + q - t;
            int ad = d < 0 ? -d : d;
            int j = lut[ad];
            float sg = (d > 0) ? 1.f : ((d < 0) ? -1.f : 0.f);
            vc[q] += s1s[j] + sg * s2s[j];
        }
        m = fmaxf(m, fmaxf(fmaxf(v[e].x, v[e].y), fmaxf(v[e].z, v[e].w)));
    }
    #pragma unroll
    for (int o = 16; o > 0; o >>= 1) m = fmaxf(m, __shfl_xor_sync(0xffffffffu, m, o));
    if ((tid & 31) == 0) red[tid >> 5] = m;
    __syncthreads();
    m = fmaxf(fmaxf(red[0], red[1]), fmaxf(red[2], red[3]));
    __syncthreads();

    float s = 0.f;
    #pragma unroll
    for (int e = 0; e < 3; e++) {
        v[e].x = __expf(v[e].x - m); v[e].y = __expf(v[e].y - m);
        v[e].z = __expf(v[e].z - m); v[e].w = __expf(v[e].w - m);
        s += v[e].x + v[e].y + v[e].z + v[e].w;
    }
    #pragma unroll
    for (int o = 16; o > 0; o >>= 1) s += __shfl_xor_sync(0xffffffffu, s, o);
    if ((tid & 31) == 0) red[tid >> 5] = s;
    __syncthreads();
    s = red[0] + red[1] + red[2] + red[3];
    float inv = 1.0f / s;
    #pragma unroll
    for (int e = 0; e < 3; e++) {
        v[e].x *= inv; v[e].y *= inv; v[e].z *= inv; v[e].w *= inv;
        p[tid + e * 128] = v[e];
    }
}

// ---------------- launch ----------------------------------------------------------
extern "C" void kernel_launch(void* const* d_in, const int* in_sizes, int n_in,
                              void* d_out, int out_size)
{
    const float* x   = (const float*)d_in[0];
    const float* Wq  = (const float*)d_in[1];
    const float* Wk  = (const float*)d_in[2];
    const float* Wv  = (const float*)d_in[3];
    const float* Wr  = (const float*)d_in[4];
    const float* rwb = (const float*)d_in[5];
    const float* rrb = (const float*)d_in[6];
    const float* Wo  = (const float*)d_in[7];
    const float* bo  = (const float*)d_in[8];
    float* out = (float*)d_out;

    uint32_t *d_xs_h, *d_xs_l, *d_wq_h, *d_wq_l, *d_wk_h, *d_wk_l;
    cudaGetSymbolAddress((void**)&d_xs_h, xs_h); cudaGetSymbolAddress((void**)&d_xs_l, xs_l);
    cudaGetSymbolAddress((void**)&d_wq_h, wq_h); cudaGetSymbolAddress((void**)&d_wq_l, wq_l);
    cudaGetSymbolAddress((void**)&d_wk_h, wk_h); cudaGetSymbolAddress((void**)&d_wk_l, wk_l);

    cudaFuncSetAttribute(mma_gemm<0>, cudaFuncAttributeMaxDynamicSharedMemorySize, SMEM_REQ);
    cudaFuncSetAttribute(mma_gemm<5>, cudaFuncAttributeMaxDynamicSharedMemorySize, SMEM_REQ);

    // prep: split inputs for bf16x3 path
    split_rows<<<(3072 * CP + 255) / 256, 256>>>(x, d_xs_h, d_xs_l, (size_t)3072 * CP);
    split_T<<<dim3(HK / 32, Cdim / 32, 1), 256>>>(Wq, d_wq_h, d_wq_l, Cdim, HK);
    split_T<<<dim3(HK / 32, Cdim / 32, 1), 256>>>(Wk, d_wk_h, d_wk_l, Cdim, HK);

    // fused Q+K projection (bf16x3, precision-critical)
    mma_gemm<0><<<dim3(16, 24, 1), 256, SMEM_REQ>>>(rwb, rrb);
    // V projection (tf32 single-pass)
    tf32_gemm<2><<<dim3(HV / 64, 24, 1), 256>>>(x, Wv, nullptr, nullptr, Cdim, Cdim, HV);

    // rank-32 rel path: u + suffix sums (replaces rk GEMM + banded rel GEMM)
    u_kernel<<<ZN * Tdim / 4, 128>>>(Wr);

    // content logits (bf16x3)
    mma_gemm<5><<<dim3(24, 12, ZN), 256, SMEM_REQ>>>(nullptr, nullptr);

    // softmax with fused rel-add
    softmax_kernel<<<ZN * Tdim, 128>>>();

    // P @ V (tf32 single-pass)
    tf32_gemm<4><<<dim3(Vdim / 64, 12, ZN), 256>>>(nullptr, nullptr, nullptr, nullptr, Tdim, Tdim, Vdim);

    // out proj (tf32 single-pass)
    tf32_gemm<3><<<dim3(HV / 64, 24, 1), 256>>>(nullptr, Wo, bo, out, HV, HV, HV);
}

// round 11
// speedup vs baseline: 1.4514x; 1.0434x over previous
#include <cuda_runtime.h>
#include <cuda_bf16.h>
#include <stdint.h>
#include <math.h>

// Problem constants
#define Bdim 2
#define Tdim 1536
#define Cdim 1536
#define Hdim 8
#define Kdim 64
#define Vdim 192
#define HK   512
#define HV   1536
#define ZN   16       // B*H
#define CP   768      // 1536/2 pairs
#define KP   32       // 64/2 pairs

// ---------------- scratch ----------------
__device__ uint32_t xs_h[(size_t)3072 * CP],  xs_l[(size_t)3072 * CP];
__device__ uint32_t wq_h[(size_t)HK * CP],    wq_l[(size_t)HK * CP];
__device__ uint32_t wk_h[(size_t)HK * CP],    wk_l[(size_t)HK * CP];
__device__ uint32_t qw_h[(size_t)ZN * Tdim * KP], qw_l[(size_t)ZN * Tdim * KP];
__device__ uint32_t kk_h[(size_t)ZN * Tdim * KP], kk_l[(size_t)ZN * Tdim * KP];
__device__ float    g_qrf[(size_t)ZN * Tdim * Kdim];          // fp32 qr (for u)
__device__ float    g_S1[(size_t)ZN * Tdim * 20];             // suffix sums (17 used)
__device__ float    g_S2[(size_t)ZN * Tdim * 20];
__device__ float    g_v [(size_t)ZN * Tdim * Vdim];           // tf32-rounded
__device__ float    g_logits[(size_t)ZN * Tdim * Tdim];       // logits -> P (tf32 after softmax)
__device__ float    g_attn[(size_t)3072 * HV];                // tf32-rounded
__device__ float    x_t [(size_t)3072 * Cdim];                // tf32-rounded copies
__device__ float    wv_t[(size_t)Cdim * HV];
__device__ float    wo_t[(size_t)HV * HV];

// ---------------- helpers ----------------
__device__ __forceinline__ uint32_t pack2(float a, float b) {
    uint32_t r;
    asm("cvt.rn.bf16x2.f32 %0, %1, %2;" : "=r"(r) : "f"(b), "f"(a));
    return r;
}
__device__ __forceinline__ void split2(float x0, float x1, uint32_t& h, uint32_t& l) {
    float h0 = __bfloat162float(__float2bfloat16(x0));
    float h1 = __bfloat162float(__float2bfloat16(x1));
    h = pack2(h0, h1);
    l = pack2(x0 - h0, x1 - h1);
}
__device__ __forceinline__ void mma_bf16(float* d, const uint32_t* a, const uint32_t* b) {
    asm volatile(
        "mma.sync.aligned.m16n8k16.row.col.f32.bf16.bf16.f32 "
        "{%0,%1,%2,%3}, {%4,%5,%6,%7}, {%8,%9}, {%0,%1,%2,%3};"
        : "+f"(d[0]), "+f"(d[1]), "+f"(d[2]), "+f"(d[3])
        : "r"(a[0]), "r"(a[1]), "r"(a[2]), "r"(a[3]), "r"(b[0]), "r"(b[1]));
}
__device__ __forceinline__ uint32_t f2tf32(float x) {
    uint32_t r;
    asm("cvt.rna.tf32.f32 %0, %1;" : "=r"(r) : "f"(x));
    return r;
}
__device__ __forceinline__ void mma_tf32(float* d, const uint32_t* a, const uint32_t* b) {
    asm volatile(
        "mma.sync.aligned.m16n8k8.row.col.f32.tf32.tf32.f32 "
        "{%0,%1,%2,%3}, {%4,%5,%6,%7}, {%8,%9}, {%0,%1,%2,%3};"
        : "+f"(d[0]), "+f"(d[1]), "+f"(d[2]), "+f"(d[3])
        : "r"(a[0]), "r"(a[1]), "r"(a[2]), "r"(a[3]), "r"(b[0]), "r"(b[1]));
}
__device__ __forceinline__ void cpa16(uint32_t dst, const void* src) {
    asm volatile("cp.async.cg.shared.global [%0], [%1], 16;" :: "r"(dst), "l"(src));
}
#define CP_COMMIT() asm volatile("cp.async.commit_group;")
__device__ __forceinline__ void ldm4(uint32_t* r, uint32_t addr) {
    asm volatile("ldmatrix.sync.aligned.m8n8.x4.shared.b16 {%0,%1,%2,%3}, [%4];"
                 : "=r"(r[0]), "=r"(r[1]), "=r"(r[2]), "=r"(r[3]) : "r"(addr));
}

// =============== bf16x3 GEMM: 128x64 tile, k-chunk 32, 2-stage (3 CTAs/SM) =======
// MODE 0: x@[Wq|Wk] -> qw(split)+qr(f32), kk(split) | 5: qw@k^T -> logits
#define AROWB 80
#define A_LO  10240
#define B_OFF 20480
#define B_LO  5120
#define STG   30720
#define SMEM_REQ (2 * STG)

template <int MODE>
__global__ __launch_bounds__(256) void mma_gemm(
    const float* __restrict__ bias0, const float* __restrict__ bias1)
{
    extern __shared__ uint8_t dsm[];

    const int z   = blockIdx.z;
    const int m0  = blockIdx.y * 128;
    const int n0  = blockIdx.x * 64;
    const int tid = threadIdx.x;
    const int lane = tid & 31, warp = tid >> 5;
    const int wm = warp >> 1, wn = warp & 1;

    const uint32_t *Ah_g, *Al_g, *Bh_g, *Bl_g;
    int ldpA, ldpB, nchunks;
    bool isQ = true;
    int n0b = n0;
    if (MODE == 0) {
        Ah_g = xs_h; Al_g = xs_l;
        isQ = (n0 < HK);
        if (isQ) { Bh_g = wq_h; Bl_g = wq_l; }
        else     { Bh_g = wk_h; Bl_g = wk_l; n0b = n0 - HK; }
        ldpA = CP; ldpB = CP; nchunks = Cdim / 32;
    } else {
        Ah_g = qw_h + (size_t)z * Tdim * KP; Al_g = qw_l + (size_t)z * Tdim * KP;
        Bh_g = kk_h + (size_t)z * Tdim * KP; Bl_g = kk_l + (size_t)z * Tdim * KP;
        ldpA = KP; ldpB = KP; nchunks = Kdim / 32;
    }

    const int cb = n0b;
    const uint32_t sb = (uint32_t)__cvta_generic_to_shared(dsm);

    const int ar = tid >> 1, ac2 = (tid & 1) * 2;
    const int br = tid >> 2, bc  = tid & 3;
    const size_t aoff0 = (size_t)(m0 + ar) * ldpA + ac2 * 4;
    const size_t boff0 = (size_t)(cb + br) * ldpB + bc * 4;
    const uint32_t adst0 = sb + ar * AROWB + ac2 * 16;
    const uint32_t bdst0 = sb + B_OFF + br * AROWB + bc * 16;

    auto fill = [&](int s, int c) {
        const uint32_t st = s * STG;
        const size_t ko = (size_t)c * 16;
        cpa16(adst0 + st,             Ah_g + aoff0 + ko);
        cpa16(adst0 + st + 16,        Ah_g + aoff0 + ko + 4);
        cpa16(adst0 + st + A_LO,      Al_g + aoff0 + ko);
        cpa16(adst0 + st + A_LO + 16, Al_g + aoff0 + ko + 4);
        cpa16(bdst0 + st,             Bh_g + boff0 + ko);
        cpa16(bdst0 + st + B_LO,      Bl_g + boff0 + ko);
        CP_COMMIT();
    };

    const int mat = lane >> 3, rIn = lane & 7;
    const int mrow = (mat & 1) * 8 + rIn;
    const int colb = (mat >> 1) * 16;
    const uint32_t aAddr = sb + (uint32_t)((wm * 32 + mrow) * AROWB + colb);
    const uint32_t bAddr = sb + (uint32_t)(B_OFF + (wn * 32 + mrow) * AROWB + colb);

    float acc[2][4][4] = {};

    fill(0, 0);
    if (nchunks > 1) fill(1, 1);

    for (int c = 0; c < nchunks; c++) {
        const int s = c & 1;
        if (c + 1 < nchunks) asm volatile("cp.async.wait_group 1;");
        else                 asm volatile("cp.async.wait_group 0;");
        __syncthreads();

        const uint32_t st = s * STG;
        #pragma unroll
        for (int kh = 0; kh < 2; kh++) {
            uint32_t ah[2][4], al[2][4], bh[2][4], bl[2][4];
            ldm4(ah[0], aAddr + st + kh * 32);
            ldm4(ah[1], aAddr + st + 16 * AROWB + kh * 32);
            ldm4(al[0], aAddr + st + A_LO + kh * 32);
            ldm4(al[1], aAddr + st + A_LO + 16 * AROWB + kh * 32);
            ldm4(bh[0], bAddr + st + kh * 32);
            ldm4(bh[1], bAddr + st + 16 * AROWB + kh * 32);
            ldm4(bl[0], bAddr + st + B_LO + kh * 32);
            ldm4(bl[1], bAddr + st + B_LO + 16 * AROWB + kh * 32);
            #pragma unroll
            for (int mi = 0; mi < 2; mi++)
                #pragma unroll
                for (int ni = 0; ni < 4; ni++) {
                    const int ng = ni >> 1, j = ni & 1;
                    uint32_t b2h[2] = { bh[ng][j], bh[ng][j + 2] };
                    uint32_t b2l[2] = { bl[ng][j], bl[ng][j + 2] };
                    mma_bf16(acc[mi][ni], ah[mi], b2h);
                    mma_bf16(acc[mi][ni], ah[mi], b2l);
                    mma_bf16(acc[mi][ni], al[mi], b2h);
                }
        }
        __syncthreads();
        if (c + 2 < nchunks) fill(s, c + 2);
    }

    // ---------------- epilogue ----------------
    #pragma unroll
    for (int mi = 0; mi < 2; mi++) {
        #pragma unroll
        for (int ni = 0; ni < 4; ni++) {
            #pragma unroll
            for (int hh = 0; hh < 2; hh++) {
                const int row = m0 + wm * 32 + mi * 16 + (lane >> 2) + hh * 8;
                const int col = cb + wn * 32 + ni * 8 + 2 * (lane & 3);
                float v0 = acc[mi][ni][hh * 2 + 0];
                float v1 = acc[mi][ni][hh * 2 + 1];

                if (MODE == 0) {
                    int bb = row / Tdim, t = row % Tdim;
                    int h = col >> 6, kw = col & 63;
                    size_t idx = (((size_t)(bb * Hdim + h)) * Tdim + t) * KP + (kw >> 1);
                    if (isQ) {
                        float q0 = v0 * 0.125f, q1 = v1 * 0.125f;
                        uint32_t hw, lw;
                        split2(q0 + bias0[col], q1 + bias0[col + 1], hw, lw);
                        qw_h[idx] = hw; qw_l[idx] = lw;
                        *(float2*)&g_qrf[(((size_t)(bb * Hdim + h)) * Tdim + t) * Kdim + kw] =
                            make_float2(q0 + bias1[col], q1 + bias1[col + 1]);
                    } else {
                        uint32_t hw, lw;
                        split2(v0, v1, hw, lw);
                        kk_h[idx] = hw; kk_l[idx] = lw;
                    }
                } else {
                    *(float2*)&g_logits[((size_t)z * Tdim + row) * Tdim + col] = make_float2(v0, v1);
                }
            }
        }
    }
}

// =============== pipelined tf32 GEMM: 128x64 tile, k-chunk 16, 3-stage ring ======
// operands pre-rounded to tf32 in global; loaders are pure cp.async
// MODE 2: x_t@wv_t -> g_v | 3: g_attn@wo_t + bo -> out | 4: P@g_v -> g_attn
#define TAROW 80           // 16 fp32 + 4 pad  (20 words)
#define TB_OFF 10240
#define TBROW 288          // 64 fp32 + 8 pad  (72 words)
#define TSTG  14848
#define TSMEM (3 * TSTG)

template <int MODE>
__global__ __launch_bounds__(256) void tf32_gemm(
    const float* __restrict__ bias0, float* __restrict__ outp)
{
    extern __shared__ uint8_t dsm[];

    const int z   = blockIdx.z;
    const int m0  = blockIdx.y * 128;
    const int n0  = blockIdx.x * 64;
    const int tid = threadIdx.x;
    const int lane = tid & 31, warp = tid >> 5;
    const int wm = warp >> 1, wn = warp & 1;

    const float *Ap, *Bp;
    int lda, ldb;
    if (MODE == 2)      { Ap = x_t;  Bp = wv_t; lda = Cdim; ldb = HV; }
    else if (MODE == 3) { Ap = g_attn; Bp = wo_t; lda = HV; ldb = HV; }
    else                { Ap = g_logits + (size_t)z * Tdim * Tdim;
                          Bp = g_v + (size_t)z * Tdim * Vdim; lda = Tdim; ldb = Vdim; }
    const int nchunks = 96;   // K = 1536 for all three

    const uint32_t sb = (uint32_t)__cvta_generic_to_shared(dsm);

    // producers: A 512 chunks -> 2/thread ; B 256 chunks -> 1/thread
    const int ar = tid >> 1, ac0 = (tid & 1) * 2;          // chunk pair
    const int br = tid >> 4, bq = tid & 15;
    const size_t aoff0 = (size_t)(m0 + ar) * lda + ac0 * 4;
    const size_t boff0 = (size_t)br * ldb + n0 + bq * 4;
    const uint32_t adst0 = sb + ar * TAROW + ac0 * 16;
    const uint32_t bdst0 = sb + TB_OFF + br * TBROW + bq * 16;

    auto fill = [&](int s, int c) {
        const uint32_t st = s * TSTG;
        const size_t ko = (size_t)c * 16;
        cpa16(adst0 + st,      Ap + aoff0 + ko);
        cpa16(adst0 + st + 16, Ap + aoff0 + ko + 4);
        cpa16(bdst0 + st,      Bp + boff0 + (size_t)c * 16 * ldb);
        CP_COMMIT();
    };

    float acc[2][4][4] = {};

    fill(0, 0);
    fill(1, 1);

    for (int c = 0; c < nchunks; c++) {
        const int s = c % 3;
        if (c + 1 < nchunks) asm volatile("cp.async.wait_group 1;");
        else                 asm volatile("cp.async.wait_group 0;");
        __syncthreads();
        if (c + 2 < nchunks) fill((c + 2) % 3, c + 2);

        const uint32_t* As = (const uint32_t*)(dsm + s * TSTG);
        const uint32_t* Bs = (const uint32_t*)(dsm + s * TSTG + TB_OFF);
        #pragma unroll
        for (int ks = 0; ks < 2; ks++) {
            const int kb = ks * 8 + (lane & 3);
            uint32_t a[2][4], b[4][2];
            const int r0 = wm * 32 + (lane >> 2);
            #pragma unroll
            for (int mi = 0; mi < 2; mi++) {
                int r = r0 + mi * 16;
                a[mi][0] = As[r * 20 + kb];
                a[mi][1] = As[(r + 8) * 20 + kb];
                a[mi][2] = As[r * 20 + kb + 4];
                a[mi][3] = As[(r + 8) * 20 + kb + 4];
            }
            #pragma unroll
            for (int ni = 0; ni < 4; ni++) {
                int n = wn * 32 + ni * 8 + (lane >> 2);
                b[ni][0] = Bs[kb * 72 + n];
                b[ni][1] = Bs[(kb + 4) * 72 + n];
            }
            #pragma unroll
            for (int mi = 0; mi < 2; mi++)
                #pragma unroll
                for (int ni = 0; ni < 4; ni++)
                    mma_tf32(acc[mi][ni], a[mi], b[ni]);
        }
    }

    #pragma unroll
    for (int mi = 0; mi < 2; mi++) {
        #pragma unroll
        for (int ni = 0; ni < 4; ni++) {
            #pragma unroll
            for (int hh = 0; hh < 2; hh++) {
                const int row = m0 + wm * 32 + mi * 16 + (lane >> 2) + hh * 8;
                const int col = n0 + wn * 32 + ni * 8 + 2 * (lane & 3);
                float v0 = acc[mi][ni][hh * 2 + 0];
                float v1 = acc[mi][ni][hh * 2 + 1];

                if (MODE == 2) {
                    int bb = row / Tdim, t = row % Tdim;
                    int h = col / Vdim, vv = col % Vdim;
                    *(float2*)&g_v[(((size_t)(bb * Hdim + h)) * Tdim + t) * Vdim + vv] =
                        make_float2(__uint_as_float(f2tf32(v0)), __uint_as_float(f2tf32(v1)));
                } else if (MODE == 3) {
                    *(float2*)&outp[(size_t)row * HV + col] = make_float2(v0 + bias0[col], v1 + bias0[col + 1]);
                } else { // MODE 4
                    int bb = z >> 3, h = z & 7;
                    *(float2*)&g_attn[((size_t)(bb * Tdim + row)) * HV + h * Vdim + col] =
                        make_float2(__uint_as_float(f2tf32(v0)), __uint_as_float(f2tf32(v1)));
                }
            }
        }
    }
}

// ---------------- prep kernels ----------------
__global__ void split_rows(const float* __restrict__ in, uint32_t* __restrict__ oh,
                           uint32_t* __restrict__ ol, size_t npairs)
{
    size_t i = (size_t)blockIdx.x * blockDim.x + threadIdx.x;
    if (i >= npairs) return;
    float2 v = ((const float2*)in)[i];
    split2(v.x, v.y, oh[i], ol[i]);
}

__global__ void split_T(const float* __restrict__ in, uint32_t* __restrict__ oh,
                        uint32_t* __restrict__ ol, int Kc, int N)
{
    __shared__ float tile[32][33];
    int k0 = blockIdx.y * 32, n0 = blockIdx.x * 32;
    int tid = threadIdx.x;
    #pragma unroll
    for (int i = 0; i < 4; i++) {
        int idx = tid + i * 256;
        int kr = idx >> 5, nn = idx & 31;
        tile[kr][nn] = in[(size_t)(k0 + kr) * N + n0 + nn];
    }
    __syncthreads();
    #pragma unroll
    for (int i = 0; i < 2; i++) {
        int idx = tid + i * 256;
        int nn = idx >> 4, kp = idx & 15;
        uint32_t h, l;
        split2(tile[2 * kp][nn], tile[2 * kp + 1][nn], h, l);
        size_t o = (size_t)(n0 + nn) * (Kc / 2) + k0 / 2 + kp;
        oh[o] = h; ol[o] = l;
    }
}

__global__ void cvt_tf32(const float* __restrict__ in, float* __restrict__ out, size_t n4)
{
    size_t i = (size_t)blockIdx.x * blockDim.x + threadIdx.x;
    if (i >= n4) return;
    float4 v = ((const float4*)in)[i];
    v.x = __uint_as_float(f2tf32(v.x)); v.y = __uint_as_float(f2tf32(v.y));
    v.z = __uint_as_float(f2tf32(v.z)); v.w = __uint_as_float(f2tf32(v.w));
    ((float4*)out)[i] = v;
}

// ---------------- u + suffix sums ----------------
__global__ void u_kernel(const float* __restrict__ Wr)
{
    __shared__ float us[4][32];
    const int warp = threadIdx.x >> 5, lane = threadIdx.x & 31;
    const int rz = blockIdx.x * 4 + warp;
    const int h = (rz / Tdim) & 7;
    const float* qr = g_qrf + (size_t)rz * Kdim;
    const float q0 = qr[lane], q1 = qr[lane + 32];
    const float* w = Wr + lane * HK + h * 64;
    float acc = 0.f;
    #pragma unroll
    for (int k = 0; k < 32; k++)
        acc += __shfl_sync(0xffffffffu, q0, k) * w[k];
    #pragma unroll
    for (int k = 0; k < 32; k++)
        acc += __shfl_sync(0xffffffffu, q1, k) * w[k + 32];
    us[warp][lane] = acc;
    __syncwarp();
    if (lane < 17) {
        float s1 = 0.f, s2 = 0.f;
        for (int i = lane; i < 16; i++) { s1 += us[warp][i]; s2 += us[warp][16 + i]; }
        g_S1[(size_t)rz * 20 + lane] = s1;
        g_S2[(size_t)rz * 20 + lane] = s2;
    }
}

// ---------------- softmax with fused rel add; writes P tf32-rounded --------------
__global__ void softmax_kernel()
{
    const int row = blockIdx.x;
    const int t = row % Tdim;
    float4* p = (float4*)(g_logits + (size_t)row * Tdim);
    const int tid = threadIdx.x;
    __shared__ float red[4];
    __shared__ float cws[16];
    __shared__ float s1s[17], s2s[17];
    __shared__ uint8_t lut[Tdim];

    if (tid < 16)
        cws[tid] = powf((float)exp(log((double)(Tdim + 1)) / 16.0), (float)(tid + 1)) - 1.0f;
    if (tid >= 16 && tid < 33) {
        int j = tid - 16;
        s1s[j] = g_S1[(size_t)row * 20 + j];
        s2s[j] = g_S2[(size_t)row * 20 + j];
    }
    __syncthreads();
    for (int d = tid; d < Tdim; d += 128) {
        float fd = (float)d;
        int j = 0;
        #pragma unroll
        for (int i = 0; i < 16; i++) j += (cws[i] <= fd);
        lut[d] = (uint8_t)j;
    }
    __syncthreads();

    float4 v[3];
    float m = -1e30f;
    #pragma unroll
    for (int e = 0; e < 3; e++) {
        v[e] = p[tid + e * 128];
        const int sbase = (tid + e * 128) * 4;
        float* vc = (float*)&v[e];
        #pragma unroll
        for (int q = 0; q < 4; q++) {
            int d = sbase + q - t;
            int ad = d < 0 ? -d : d;
            int j = lut[ad];
            float sg = (d > 0) ? 1.f : ((d < 0) ? -1.f : 0.f);
            vc[q] += s1s[j] + sg * s2s[j];
        }
        m = fmaxf(m, fmaxf(fmaxf(v[e].x, v[e].y), fmaxf(v[e].z, v[e].w)));
    }
    #pragma unroll
    for (int o = 16; o > 0; o >>= 1) m = fmaxf(m, __shfl_xor_sync(0xffffffffu, m, o));
    if ((tid & 31) == 0) red[tid >> 5] = m;
    __syncthreads();
    m = fmaxf(fmaxf(red[0], red[1]), fmaxf(red[2], red[3]));
    __syncthreads();

    float s = 0.f;
    #pragma unroll
    for (int e = 0; e < 3; e++) {
        v[e].x = __expf(v[e].x - m); v[e].y = __expf(v[e].y - m);
        v[e].z = __expf(v[e].z - m); v[e].w = __expf(v[e].w - m);
        s += v[e].x + v[e].y + v[e].z + v[e].w;
    }
    #pragma unroll
    for (int o = 16; o > 0; o >>= 1) s += __shfl_xor_sync(0xffffffffu, s, o);
    if ((tid & 31) == 0) red[tid >> 5] = s;
    __syncthreads();
    s = red[0] + red[1] + red[2] + red[3];
    float inv = 1.0f / s;
    #pragma unroll
    for (int e = 0; e < 3; e++) {
        v[e].x = __uint_as_float(f2tf32(v[e].x * inv));
        v[e].y = __uint_as_float(f2tf32(v[e].y * inv));
        v[e].z = __uint_as_float(f2tf32(v[e].z * inv));
        v[e].w = __uint_as_float(f2tf32(v[e].w * inv));
        p[tid + e * 128] = v[e];
    }
}

// ---------------- launch ----------------------------------------------------------
extern "C" void kernel_launch(void* const* d_in, const int* in_sizes, int n_in,
                              void* d_out, int out_size)
{
    const float* x   = (const float*)d_in[0];
    const float* Wq  = (const float*)d_in[1];
    const float* Wk  = (const float*)d_in[2];
    const float* Wv  = (const float*)d_in[3];
    const float* Wr  = (const float*)d_in[4];
    const float* rwb = (const float*)d_in[5];
    const float* rrb = (const float*)d_in[6];
    const float* Wo  = (const float*)d_in[7];
    const float* bo  = (const float*)d_in[8];
    float* out = (float*)d_out;

    uint32_t *d_xs_h, *d_xs_l, *d_wq_h, *d_wq_l, *d_wk_h, *d_wk_l;
    float *d_xt, *d_wvt, *d_wot;
    cudaGetSymbolAddress((void**)&d_xs_h, xs_h); cudaGetSymbolAddress((void**)&d_xs_l, xs_l);
    cudaGetSymbolAddress((void**)&d_wq_h, wq_h); cudaGetSymbolAddress((void**)&d_wq_l, wq_l);
    cudaGetSymbolAddress((void**)&d_wk_h, wk_h); cudaGetSymbolAddress((void**)&d_wk_l, wk_l);
    cudaGetSymbolAddress((void**)&d_xt, x_t);
    cudaGetSymbolAddress((void**)&d_wvt, wv_t);
    cudaGetSymbolAddress((void**)&d_wot, wo_t);

    cudaFuncSetAttribute(mma_gemm<0>, cudaFuncAttributeMaxDynamicSharedMemorySize, SMEM_REQ);
    cudaFuncSetAttribute(mma_gemm<5>, cudaFuncAttributeMaxDynamicSharedMemorySize, SMEM_REQ);
    cudaFuncSetAttribute(tf32_gemm<2>, cudaFuncAttributeMaxDynamicSharedMemorySize, TSMEM);
    cudaFuncSetAttribute(tf32_gemm<3>, cudaFuncAttributeMaxDynamicSharedMemorySize, TSMEM);
    cudaFuncSetAttribute(tf32_gemm<4>, cudaFuncAttributeMaxDynamicSharedMemorySize, TSMEM);

    // prep
    split_rows<<<(3072 * CP + 255) / 256, 256>>>(x, d_xs_h, d_xs_l, (size_t)3072 * CP);
    split_T<<<dim3(HK / 32, Cdim / 32, 1), 256>>>(Wq, d_wq_h, d_wq_l, Cdim, HK);
    split_T<<<dim3(HK / 32, Cdim / 32, 1), 256>>>(Wk, d_wk_h, d_wk_l, Cdim, HK);
    cvt_tf32<<<(3072 * Cdim / 4 + 255) / 256, 256>>>(x, d_xt, (size_t)3072 * Cdim / 4);
    cvt_tf32<<<(Cdim * HV / 4 + 255) / 256, 256>>>(Wv, d_wvt, (size_t)Cdim * HV / 4);
    cvt_tf32<<<(HV * HV / 4 + 255) / 256, 256>>>(Wo, d_wot, (size_t)HV * HV / 4);

    // fused Q+K projection (bf16x3)
    mma_gemm<0><<<dim3(16, 24, 1), 256, SMEM_REQ>>>(rwb, rrb);
    // V projection (tf32 pipelined)
    tf32_gemm<2><<<dim3(HV / 64, 24, 1), 256, TSMEM>>>(nullptr, nullptr);

    // rank-32 rel path
    u_kernel<<<ZN * Tdim / 4, 128>>>(Wr);

    // content logits (bf16x3)
    mma_gemm<5><<<dim3(24, 12, ZN), 256, SMEM_REQ>>>(nullptr, nullptr);

    // softmax with fused rel-add (writes tf32 P)
    softmax_kernel<<<ZN * Tdim, 128>>>();

    // P @ V (tf32 pipelined)
    tf32_gemm<4><<<dim3(Vdim / 64, 12, ZN), 256, TSMEM>>>(nullptr, nullptr);

    // out proj (tf32 pipelined)
    tf32_gemm<3><<<dim3(HV / 64, 24, 1), 256, TSMEM>>>(bo, out);
}